// round 14
// baseline (speedup 1.0000x reference)
#include <cuda_runtime.h>
#include <cuda_fp16.h>
#include <math.h>
#include <stdint.h>

// Problem dims
#define BB 2048
#define SS 128
#define VV 128
#define EE 300
#define HH 512
#define H3 1536
#define KIH 832              // padded 812
#define KF  384              // fc1-out / fc2-K padding

// ---------------- scratch (device globals) ----------------
__device__ float  g_ug[BB * 2048];           // [u | gh]
__device__ float  g_gi[BB * H3];
__device__ __half g_hid_h[BB * HH];
__device__ __half g_wc_h[2048 * HH];         // [W2; gru_w_hh]
__device__ __half g_w1_h[HH * HH];
__device__ __half g_wih_h[H3 * KIH];
__device__ __half g_gin_h[BB * KIH];
__device__ __half g_hn_h[BB * HH];
__device__ __half g_f1_h[KF * HH];
__device__ __half g_f2_h[VV * KF];
__device__ __half g_a1_h[BB * KF];
__device__ float  g_bc[2048];
__device__ float  g_bfc1[KF];

// ================= helpers =================
__device__ __forceinline__ uint32_t smem_u32(const void* p) {
    uint32_t a;
    asm("{ .reg .u64 t; cvta.to.shared.u64 t, %1; cvt.u32.u64 %0, t; }" : "=r"(a) : "l"(p));
    return a;
}
__device__ __forceinline__ void ldm_x4(uint32_t* r, uint32_t addr) {
    asm volatile("ldmatrix.sync.aligned.m8n8.x4.shared.b16 {%0,%1,%2,%3}, [%4];"
        : "=r"(r[0]), "=r"(r[1]), "=r"(r[2]), "=r"(r[3]) : "r"(addr));
}
__device__ __forceinline__ void mma_h(float* c, const uint32_t* a, const uint32_t* b) {
    asm volatile("mma.sync.aligned.m16n8k16.row.col.f32.f16.f16.f32 "
        "{%0,%1,%2,%3}, {%4,%5,%6,%7}, {%8,%9}, {%0,%1,%2,%3};"
        : "+f"(c[0]), "+f"(c[1]), "+f"(c[2]), "+f"(c[3])
        : "r"(a[0]), "r"(a[1]), "r"(a[2]), "r"(a[3]), "r"(b[0]), "r"(b[1]));
}
__device__ __forceinline__ void cpasync16(uint32_t dst, const void* src) {
    asm volatile("cp.async.cg.shared.global [%0], [%1], 16;" :: "r"(dst), "l"(src) : "memory");
}
#define CP_COMMIT() asm volatile("cp.async.commit_group;" ::: "memory")
#define CP_WAIT0()  asm volatile("cp.async.wait_group 0;" ::: "memory")

__device__ __forceinline__ uint32_t pack_h2(float a, float b) {
    __half2 t = __floats2half2_rn(a, b);
    return *(uint32_t*)&t;
}
__device__ __forceinline__ float tanh_fast(float x) {
    float y;
    asm("tanh.approx.f32 %0, %1;" : "=f"(y) : "f"(x));
    return y;
}
__device__ __forceinline__ float tanh_acc(float x) {
    x = fminf(fmaxf(x, -15.f), 15.f);
    float e = __expf(2.f * x);
    return __fdividef(e - 1.f, e + 1.f);
}
__device__ __forceinline__ float sigmoid_fast(float x) {
    return __fdividef(1.f, 1.f + __expf(-x));
}

// ================= single merged prep kernel =================
#define PB_W1  1024
#define PB_WC  (PB_W1 + 4096)
#define PB_HID (PB_W1 + 8192)
#define PB_WIH (PB_HID + 4992)
#define PB_F1  (PB_WIH + 768)
#define PB_F2  (PB_F1 + 192)
#define PB_BC  (PB_F2 + 8)
#define PB_BF  (PB_BC + 2)
__global__ void prep_all(const float* __restrict__ w1, const float* __restrict__ w2,
                         const float* __restrict__ whh, const float* __restrict__ hid,
                         const float* __restrict__ wih,
                         const float* __restrict__ fc1w, const float* __restrict__ fc2w,
                         const float* __restrict__ w2b, const float* __restrict__ bhh,
                         const float* __restrict__ f1b,
                         __half* __restrict__ w1_h, __half* __restrict__ wc_h,
                         __half* __restrict__ hid_h, __half* __restrict__ wih_h,
                         __half* __restrict__ f1_h, __half* __restrict__ f2_h,
                         float* __restrict__ bc, float* __restrict__ bfc1)
{
    int blk = blockIdx.x, t = threadIdx.x;
    if (blk < PB_W1) {
        int i = blk * 256 + t;
        w1_h[i] = __float2half_rn(w1[i]);
    } else if (blk < PB_WC) {
        int i = (blk - PB_W1) * 256 + t;
        float v = (i < 512 * 512) ? w2[i] : whh[i - 512 * 512];
        wc_h[i] = __float2half_rn(v);
    } else if (blk < PB_HID) {
        int i = (blk - PB_WC) * 256 + t;
        hid_h[i] = __float2half_rn(hid[i]);
    } else if (blk < PB_WIH) {
        int i = (blk - PB_HID) * 256 + t;
        int r = i / KIH, c = i - r * KIH;
        wih_h[i] = __float2half_rn((c < 812) ? wih[(size_t)r * 812 + c] : 0.f);
    } else if (blk < PB_F1) {
        int i = (blk - PB_WIH) * 256 + t;
        int r = i >> 9;
        f1_h[i] = __float2half_rn((r < 300) ? fc1w[i] : 0.f);
    } else if (blk < PB_F2) {
        int i = (blk - PB_F1) * 256 + t;
        int r = i / KF, c = i - r * KF;
        f2_h[i] = __float2half_rn((c < 300) ? fc2w[(size_t)r * 300 + c] : 0.f);
    } else if (blk < PB_BC) {
        int i = (blk - PB_F2) * 256 + t;
        bc[i] = (i < 512) ? w2b[i] : bhh[i - 512];
    } else if (blk < PB_BF) {
        int i = (blk - PB_BC) * 256 + t;
        if (i < KF) bfc1[i] = (i < 300) ? f1b[i] : 0.f;
    }
}

// ================= HMMA fp16 single-pass GEMM =================
// C[M,N] = A[M,K] @ B[N,K]^T + bias ; CTA 64Mx128N, 8 warps 2Mx4N.
#define HG_BUF  24576            // A 8K | B 16K
#define HG_SMEM 49152
template<int OUT>
__global__ void __launch_bounds__(256) hgemm(
    const __half* __restrict__ A, const __half* __restrict__ B,
    const float* __restrict__ bias, float* __restrict__ C,
    __half* __restrict__ Ch, int K, int lda, int ldc)
{
    extern __shared__ __align__(128) char sm[];
    const uint32_t smb = smem_u32(sm);
    const int tid = threadIdx.x, wid = tid >> 5, lane = tid & 31;
    const int mb = wid & 1, nw = wid >> 1;
    const int m0 = blockIdx.y * 64, n0 = blockIdx.x * 128;
    const int nk = K >> 6;

    auto prefetch = [&](int kc) {
        uint32_t base = smb + (uint32_t)(kc & 1) * HG_BUF;
        #pragma unroll
        for (int it = 0; it < 2; it++) {
            int idx = tid + it * 256;
            int r = idx >> 3, c = idx & 7;
            uint32_t dst = base + r * 128 + ((uint32_t)(c ^ (r & 7)) << 4);
            cpasync16(dst, A + (size_t)(m0 + r) * lda + kc * 64 + c * 8);
        }
        #pragma unroll
        for (int it = 0; it < 4; it++) {
            int idx = tid + it * 256;
            int r = idx >> 3, c = idx & 7;
            uint32_t dst = base + 8192 + r * 128 + ((uint32_t)(c ^ (r & 7)) << 4);
            cpasync16(dst, B + (size_t)(n0 + r) * K + kc * 64 + c * 8);
        }
        CP_COMMIT();
    };

    float acc[2][4][4] = {};
    const int aswz = lane & 7;
    prefetch(0);

    for (int kc = 0; kc < nk; kc++) {
        CP_WAIT0();
        __syncthreads();
        if (kc + 1 < nk) prefetch(kc + 1);
        uint32_t base = smb + (uint32_t)(kc & 1) * HG_BUF;
        uint32_t aB[2], bB[2];
        #pragma unroll
        for (int f = 0; f < 2; f++) {
            aB[f] = base + (mb * 32 + f * 16 + (lane & 15)) * 128;
            bB[f] = base + 8192 + (nw * 32 + f * 16 + (lane & 15)) * 128;
        }
        #pragma unroll
        for (int ks = 0; ks < 4; ks++) {
            int chunk = ks * 2 + (lane >> 4);
            uint32_t coff = (uint32_t)(chunk ^ aswz) << 4;
            uint32_t ah[2][4], bh[2][4];
            #pragma unroll
            for (int f = 0; f < 2; f++) {
                ldm_x4(ah[f], aB[f] + coff);
                ldm_x4(bh[f], bB[f] + coff);
            }
            #pragma unroll
            for (int m = 0; m < 2; m++)
                #pragma unroll
                for (int f2 = 0; f2 < 2; f2++)
                    #pragma unroll
                    for (int sel = 0; sel < 2; sel++) {
                        uint32_t bf[2] = { bh[f2][sel], bh[f2][sel + 2] };
                        mma_h(acc[m][f2 * 2 + sel], ah[m], bf);
                    }
        }
    }

    #pragma unroll
    for (int f = 0; f < 2; f++) {
        int r0 = m0 + mb * 32 + f * 16 + (lane >> 2);
        int r1 = r0 + 8;
        #pragma unroll
        for (int n8 = 0; n8 < 4; n8++) {
            int col = n0 + nw * 32 + n8 * 8 + ((lane & 3) << 1);
            float b0 = bias[col], b1 = bias[col + 1];
            float v00 = acc[f][n8][0] + b0, v01 = acc[f][n8][1] + b1;
            float v10 = acc[f][n8][2] + b0, v11 = acc[f][n8][3] + b1;
            if (OUT == 0) {
                *(float2*)&C[(size_t)r0 * ldc + col] = make_float2(v00, v01);
                *(float2*)&C[(size_t)r1 * ldc + col] = make_float2(v10, v11);
            } else {
                v00 = (v00 > 0.f) ? v00 : 0.01f * v00;
                v01 = (v01 > 0.f) ? v01 : 0.01f * v01;
                v10 = (v10 > 0.f) ? v10 : 0.01f * v10;
                v11 = (v11 > 0.f) ? v11 : 0.01f * v11;
                *(uint32_t*)&Ch[(size_t)r0 * ldc + col] = pack_h2(v00, v01);
                *(uint32_t*)&Ch[(size_t)r1 * ldc + col] = pack_h2(v10, v11);
            }
        }
    }
}

// ================= fused attention: logits + softmax + ctx + emb =================
// 512 threads, 16 warps in 4M x 4N (warp tile 32x32). CTA = 128 rows = one b.
#define SA       0                    // 128 x 1024 B = 131072
#define SB       131072               // 2 bufs x 16384
#define UVW_OFF  163840               // float2[512] = 4096 B
#define PART_OFF 167936               // float[512]  = 2048 B
#define SW_OFF   169984               // float[128]  = 512 B
#define RED_OFF  170496               // float[512]  = 2048 B
#define ATT_SMEM 172544

__global__ void __launch_bounds__(512) attn_fused(
    const float* __restrict__ enc,
    const __half* __restrict__ w1h,
    const float* __restrict__ W1b, const float* __restrict__ ug,
    const float* __restrict__ Vw, const float* __restrict__ Vb,
    const int* __restrict__ x, const float* __restrict__ emb_table,
    __half* __restrict__ ginh)
{
    extern __shared__ __align__(128) char sm[];
    const uint32_t smb = smem_u32(sm);
    const int tid = threadIdx.x, wid = tid >> 5, lane = tid & 31;
    const int b = blockIdx.x;
    const int mb = wid & 3, nw = wid >> 2;

    auto prefetch = [&](int itc) {
        int nt = itc >> 3, kc = itc & 7, buf = itc & 1;
        #pragma unroll
        for (int it2 = 0; it2 < 2; it2++) {
            int idx = tid + it2 * 512;
            int r = idx >> 3, c = idx & 7;
            uint32_t dst = smb + SB + buf * 16384 + r * 128 + ((uint32_t)(c ^ (r & 7)) << 4);
            cpasync16(dst, w1h + (size_t)(nt * 128 + r) * HH + kc * 64 + c * 8);
        }
        CP_COMMIT();
    };
    prefetch(0);

    float2* uvw = (float2*)(sm + UVW_OFF);
    if (tid < HH)
        uvw[tid] = make_float2(ug[(size_t)b * 2048 + tid] + W1b[tid], Vw[tid]);

    // A slab: 128 x 512 fp32 -> fp16, swizzled (row stride 1024 B)
    #pragma unroll 4
    for (int it = 0; it < 16; it++) {
        int idx = tid + it * 512;
        int r = idx >> 6, c = idx & 63;
        const float4* src = (const float4*)(enc + (size_t)(b * SS + r) * HH + c * 8);
        float4 v0 = src[0], v1 = src[1];
        uint4 hv;
        hv.x = pack_h2(v0.x, v0.y); hv.y = pack_h2(v0.z, v0.w);
        hv.z = pack_h2(v1.x, v1.y); hv.w = pack_h2(v1.z, v1.w);
        uint32_t off = (uint32_t)(r * 1024 + ((c ^ (r & 7)) << 4));
        *(uint4*)(sm + SA + off) = hv;
    }

    const int aswz = lane & 7;
    uint32_t aB[2], bB[2];
    #pragma unroll
    for (int f = 0; f < 2; f++) {
        aB[f] = smb + SA + (mb * 32 + f * 16 + (lane & 15)) * 1024;
        bB[f] = smb + SB + (nw * 32 + f * 16 + (lane & 15)) * 128;
    }

    float acc[2][4][4] = {};
    float rp[4] = {};

    for (int itc = 0; itc < 32; itc++) {
        const int nt = itc >> 3, kc = itc & 7, buf = itc & 1;
        CP_WAIT0();
        __syncthreads();
        if (itc < 31) prefetch(itc + 1);

        #pragma unroll
        for (int ks = 0; ks < 4; ks++) {
            int achunk = kc * 8 + ks * 2 + (lane >> 4);
            uint32_t acoff = (uint32_t)(achunk ^ aswz) << 4;
            int bchunk = ks * 2 + (lane >> 4);
            uint32_t bcoff = (uint32_t)(bchunk ^ aswz) << 4;
            uint32_t ah[2][4], bh[2][4];
            #pragma unroll
            for (int f = 0; f < 2; f++) {
                ldm_x4(ah[f], aB[f] + acoff);
                ldm_x4(bh[f], bB[f] + buf * 16384 + bcoff);
            }
            #pragma unroll
            for (int f = 0; f < 2; f++)
                #pragma unroll
                for (int f2 = 0; f2 < 2; f2++)
                    #pragma unroll
                    for (int sel = 0; sel < 2; sel++) {
                        uint32_t bf[2] = { bh[f2][sel], bh[f2][sel + 2] };
                        mma_h(acc[f][f2 * 2 + sel], ah[f], bf);
                    }
        }

        if (kc == 7) {
            #pragma unroll
            for (int f = 0; f < 2; f++)
                #pragma unroll
                for (int n8 = 0; n8 < 4; n8++) {
                    int n = nt * 128 + nw * 32 + n8 * 8 + ((lane & 3) << 1);
                    float2 u0 = uvw[n], u1 = uvw[n + 1];
                    rp[f * 2]     += tanh_fast(acc[f][n8][0] + u0.x) * u0.y
                                   + tanh_fast(acc[f][n8][1] + u1.x) * u1.y;
                    rp[f * 2 + 1] += tanh_fast(acc[f][n8][2] + u0.x) * u0.y
                                   + tanh_fast(acc[f][n8][3] + u1.x) * u1.y;
                    acc[f][n8][0] = acc[f][n8][1] = acc[f][n8][2] = acc[f][n8][3] = 0.f;
                }
        }
    }

    #pragma unroll
    for (int i = 0; i < 4; i++) {
        rp[i] += __shfl_xor_sync(0xffffffffu, rp[i], 1);
        rp[i] += __shfl_xor_sync(0xffffffffu, rp[i], 2);
    }
    float* part = (float*)(sm + PART_OFF);
    if ((lane & 3) == 0) {
        #pragma unroll
        for (int f = 0; f < 2; f++) {
            int row = mb * 32 + f * 16 + (lane >> 2);
            part[nw * 128 + row]     = rp[f * 2];
            part[nw * 128 + row + 8] = rp[f * 2 + 1];
        }
    }
    __syncthreads();

    // logits + softmax (128 values, 512-thread reductions)
    float* w   = (float*)(sm + SW_OFF);
    float* red = (float*)(sm + RED_OFF);
    float lg = -1e30f;
    if (tid < 128)
        lg = part[tid] + part[128 + tid] + part[256 + tid] + part[384 + tid] + Vb[0];
    red[tid] = lg;
    __syncthreads();
    for (int s = 256; s > 0; s >>= 1) {
        if (tid < s) red[tid] = fmaxf(red[tid], red[tid + s]);
        __syncthreads();
    }
    float mx = red[0];
    __syncthreads();
    float e = (tid < 128) ? __expf(lg - mx) : 0.f;
    red[tid] = e;
    __syncthreads();
    for (int s = 256; s > 0; s >>= 1) {
        if (tid < s) red[tid] += red[tid + s];
        __syncthreads();
    }
    float inv = 1.f / red[0];
    if (tid < 128) w[tid] = e * inv;
    __syncthreads();

    // ctx from resident fp16 slab: 1 col per thread
    {
        int h0 = tid;                       // 0..511
        int chunk = h0 >> 3;
        uint32_t byte_in = (uint32_t)(h0 & 7) * 2;
        float c0 = 0.f;
        #pragma unroll 8
        for (int s = 0; s < SS; s++) {
            uint32_t addr = (uint32_t)(s * 1024 + (((uint32_t)(chunk ^ (s & 7))) << 4) + byte_in);
            __half hv = *(__half*)(sm + SA + addr);
            c0 = fmaf(w[s], __half2float(hv), c0);
        }
        ginh[(size_t)b * KIH + h0] = __float2half_rn(c0);
    }

    // emb gather -> gin[:, 512:832] (300 real + 20 pad)
    if (tid < 320) {
        int tok = x[b];
        float v = (tid < EE) ? emb_table[(size_t)tok * EE + tid] : 0.f;
        ginh[(size_t)b * KIH + HH + tid] = __float2half_rn(v);
    }
}

// ---------------- GRU pointwise ----------------
__global__ void gru_pointwise(const float* __restrict__ gi,
                              const float* __restrict__ ug,
                              const float* __restrict__ h0,
                              float* __restrict__ hout,
                              __half* __restrict__ hnh)
{
    int i = blockIdx.x * blockDim.x + threadIdx.x;
    if (i >= BB * HH) return;
    int b = i >> 9, h = i & 511;
    size_t gib = (size_t)b * H3 + h;
    size_t ghb = (size_t)b * 2048 + 512 + h;
    float i_r = gi[gib], i_z = gi[gib + HH], i_n = gi[gib + 2 * HH];
    float h_r = ug[ghb], h_z = ug[ghb + HH], h_n = ug[ghb + 2 * HH];
    float r = sigmoid_fast(i_r + h_r);
    float z = sigmoid_fast(i_z + h_z);
    float n = tanh_acc(i_n + r * h_n);
    float hn = (1.f - z) * n + z * h0[i];
    hout[i] = hn;
    hnh[i] = __float2half_rn(hn);
}

// ---------------- launch ----------------
extern "C" void kernel_launch(void* const* d_in, const int* in_sizes, int n_in,
                              void* d_out, int out_size)
{
    const int*   x        = (const int*)  d_in[0];
    const float* hidden   = (const float*)d_in[1];
    const float* enc      = (const float*)d_in[2];
    const float* emb_t    = (const float*)d_in[3];
    const float* W1_w     = (const float*)d_in[4];
    const float* W1_b     = (const float*)d_in[5];
    const float* W2_w     = (const float*)d_in[6];
    const float* W2_b     = (const float*)d_in[7];
    const float* V_w      = (const float*)d_in[8];
    const float* V_b      = (const float*)d_in[9];
    const float* gru_w_ih = (const float*)d_in[10];
    const float* gru_w_hh = (const float*)d_in[11];
    const float* gru_b_ih = (const float*)d_in[12];
    const float* gru_b_hh = (const float*)d_in[13];
    const float* fc1_w    = (const float*)d_in[14];
    const float* fc1_b    = (const float*)d_in[15];
    const float* fc2_w    = (const float*)d_in[16];
    const float* fc2_b    = (const float*)d_in[17];

    float* y_out = (float*)d_out;
    float* h_out = y_out + (size_t)BB * VV;

    float *p_ug, *p_gi, *p_bc, *p_bfc1;
    __half *p_hid, *p_wc, *p_w1, *p_wih, *p_gin, *p_hn, *p_f1, *p_f2, *p_a1;
    cudaGetSymbolAddress((void**)&p_ug, g_ug);
    cudaGetSymbolAddress((void**)&p_gi, g_gi);
    cudaGetSymbolAddress((void**)&p_bc, g_bc);
    cudaGetSymbolAddress((void**)&p_bfc1, g_bfc1);
    cudaGetSymbolAddress((void**)&p_hid, g_hid_h);
    cudaGetSymbolAddress((void**)&p_wc, g_wc_h);
    cudaGetSymbolAddress((void**)&p_w1, g_w1_h);
    cudaGetSymbolAddress((void**)&p_wih, g_wih_h);
    cudaGetSymbolAddress((void**)&p_gin, g_gin_h);
    cudaGetSymbolAddress((void**)&p_hn, g_hn_h);
    cudaGetSymbolAddress((void**)&p_f1, g_f1_h);
    cudaGetSymbolAddress((void**)&p_f2, g_f2_h);
    cudaGetSymbolAddress((void**)&p_a1, g_a1_h);

    cudaFuncSetAttribute(attn_fused, cudaFuncAttributeMaxDynamicSharedMemorySize, ATT_SMEM);
    cudaFuncSetAttribute(hgemm<0>, cudaFuncAttributeMaxDynamicSharedMemorySize, HG_SMEM);
    cudaFuncSetAttribute(hgemm<1>, cudaFuncAttributeMaxDynamicSharedMemorySize, HG_SMEM);

    // 1: merged prep
    prep_all<<<PB_BF, 256>>>(W1_w, W2_w, gru_w_hh, hidden, gru_w_ih, fc1_w, fc2_w,
                             W2_b, gru_b_hh, fc1_b,
                             p_w1, p_wc, p_hid, p_wih, p_f1, p_f2, p_bc, p_bfc1);
    // 2: ug = h0 @ [W2; gru_w_hh]^T + bias
    hgemm<0><<<dim3(2048 / 128, BB / 64), 256, HG_SMEM>>>(
        p_hid, p_wc, p_bc, p_ug, nullptr, 512, 512, 2048);
    // 3: fused attention (+softmax+ctx+emb), 512 threads
    attn_fused<<<BB, 512, ATT_SMEM>>>(enc, p_w1, W1_b, p_ug, V_w, V_b, x, emb_t, p_gin);
    // 4: gi = gin @ gru_w_ih^T + gru_b_ih
    hgemm<0><<<dim3(H3 / 128, BB / 64), 256, HG_SMEM>>>(
        p_gin, p_wih, gru_b_ih, p_gi, nullptr, KIH, KIH, H3);
    // 5: GRU pointwise
    gru_pointwise<<<(BB * HH + 255) / 256, 256>>>(p_gi, p_ug, hidden, h_out, p_hn);
    // 6: fc1
    hgemm<1><<<dim3(KF / 128, BB / 64), 256, HG_SMEM>>>(
        p_hn, p_f1, p_bfc1, nullptr, p_a1, 512, 512, KF);
    // 7: fc2
    hgemm<0><<<dim3(VV / 128, BB / 64), 256, HG_SMEM>>>(
        p_a1, p_f2, fc2_b, y_out, nullptr, KF, KF, VV);
}